// round 1
// baseline (speedup 1.0000x reference)
#include <cuda_runtime.h>

#define NN 200000

// Scratch (alloc-free: __device__ globals)
__device__ float  g_deg[NN];        // degree incl. self-loop
__device__ float  g_dis[NN];        // deg^{-1/2}
__device__ float4 g_h1[NN * 2];     // layer-1 features after x@W1, 8 f32/node
__device__ float4 g_agg1[NN * 2];   // layer-1 aggregation buffer
__device__ float4 g_h2[NN];         // layer-2 features after relu(.)@W2, 4 f32/node

__device__ __forceinline__ void red_add_f32(float* p, float v) {
    asm volatile("red.global.add.f32 [%0], %1;" :: "l"(p), "f"(v) : "memory");
}
__device__ __forceinline__ void red_add_v4(float4* p, float a, float b, float c, float d) {
    asm volatile("red.global.add.v4.f32 [%0], {%1, %2, %3, %4};"
                 :: "l"(p), "f"(a), "f"(b), "f"(c), "f"(d) : "memory");
}

// --- 1. init degree with self-loop contribution -----------------------------
__global__ void k_init_deg(int n) {
    int i = blockIdx.x * blockDim.x + threadIdx.x;
    if (i < n) g_deg[i] = 1.0f;
}

// --- 2. count in-degree at dst ----------------------------------------------
__global__ void k_count_deg(const int* __restrict__ dst, int e) {
    int i = blockIdx.x * blockDim.x + threadIdx.x;
    if (i < e) red_add_f32(&g_deg[dst[i]], 1.0f);
}

// --- 3. per-node: dis, h1 = x@W1, agg1 init = self-loop term ------------------
__global__ void k_node1(const float* __restrict__ x,
                        const float* __restrict__ W1,
                        int n) {
    int i = blockIdx.x * blockDim.x + threadIdx.x;
    if (i >= n) return;
    float d   = g_deg[i];
    float inv = 1.0f / d;               // dis^2 for self-loop norm
    g_dis[i]  = rsqrtf(d);
    float x0 = x[2 * i], x1 = x[2 * i + 1];
    float h[8];
#pragma unroll
    for (int j = 0; j < 8; j++)
        h[j] = x0 * __ldg(&W1[j]) + x1 * __ldg(&W1[8 + j]);
    float4 a = make_float4(h[0], h[1], h[2], h[3]);
    float4 b = make_float4(h[4], h[5], h[6], h[7]);
    g_h1[2 * i]     = a;
    g_h1[2 * i + 1] = b;
    g_agg1[2 * i]     = make_float4(a.x * inv, a.y * inv, a.z * inv, a.w * inv);
    g_agg1[2 * i + 1] = make_float4(b.x * inv, b.y * inv, b.z * inv, b.w * inv);
}

// --- 4. layer-1 edge scatter --------------------------------------------------
__global__ void k_edge1(const int* __restrict__ src,
                        const int* __restrict__ dst, int e) {
    int i = blockIdx.x * blockDim.x + threadIdx.x;
    if (i >= e) return;
    int s = src[i], t = dst[i];
    float nrm = __ldg(&g_dis[s]) * __ldg(&g_dis[t]);
    float4 a = __ldg(&g_h1[2 * s]);
    float4 b = __ldg(&g_h1[2 * s + 1]);
    red_add_v4(&g_agg1[2 * t],     a.x * nrm, a.y * nrm, a.z * nrm, a.w * nrm);
    red_add_v4(&g_agg1[2 * t + 1], b.x * nrm, b.y * nrm, b.z * nrm, b.w * nrm);
}

// --- 5. per-node: relu(agg1+b1)@W2, init out = self-loop term + b2 ------------
__global__ void k_node2(const float* __restrict__ W2,
                        const float* __restrict__ b1,
                        const float* __restrict__ b2,
                        float4* __restrict__ out, int n) {
    int i = blockIdx.x * blockDim.x + threadIdx.x;
    if (i >= n) return;
    float4 a = g_agg1[2 * i];
    float4 b = g_agg1[2 * i + 1];
    float v[8] = {
        fmaxf(a.x + __ldg(&b1[0]), 0.0f), fmaxf(a.y + __ldg(&b1[1]), 0.0f),
        fmaxf(a.z + __ldg(&b1[2]), 0.0f), fmaxf(a.w + __ldg(&b1[3]), 0.0f),
        fmaxf(b.x + __ldg(&b1[4]), 0.0f), fmaxf(b.y + __ldg(&b1[5]), 0.0f),
        fmaxf(b.z + __ldg(&b1[6]), 0.0f), fmaxf(b.w + __ldg(&b1[7]), 0.0f)
    };
    float h[4] = {0.0f, 0.0f, 0.0f, 0.0f};
#pragma unroll
    for (int k = 0; k < 8; k++) {
#pragma unroll
        for (int j = 0; j < 4; j++)
            h[j] = fmaf(v[k], __ldg(&W2[k * 4 + j]), h[j]);
    }
    float4 h4 = make_float4(h[0], h[1], h[2], h[3]);
    g_h2[i] = h4;
    float inv = 1.0f / g_deg[i];
    out[i] = make_float4(h4.x * inv + __ldg(&b2[0]),
                         h4.y * inv + __ldg(&b2[1]),
                         h4.z * inv + __ldg(&b2[2]),
                         h4.w * inv + __ldg(&b2[3]));
}

// --- 6. layer-2 edge scatter (into d_out directly) ----------------------------
__global__ void k_edge2(const int* __restrict__ src,
                        const int* __restrict__ dst,
                        float4* __restrict__ out, int e) {
    int i = blockIdx.x * blockDim.x + threadIdx.x;
    if (i >= e) return;
    int s = src[i], t = dst[i];
    float nrm = __ldg(&g_dis[s]) * __ldg(&g_dis[t]);
    float4 h = __ldg(&g_h2[s]);
    red_add_v4(&out[t], h.x * nrm, h.y * nrm, h.z * nrm, h.w * nrm);
}

extern "C" void kernel_launch(void* const* d_in, const int* in_sizes, int n_in,
                              void* d_out, int out_size) {
    const float* x  = (const float*)d_in[0];
    const int*   ei = (const int*)d_in[1];
    const float* W1 = (const float*)d_in[2];
    const float* b1 = (const float*)d_in[3];
    const float* W2 = (const float*)d_in[4];
    const float* b2 = (const float*)d_in[5];
    float4* out = (float4*)d_out;

    int n = in_sizes[0] / 2;     // x is [N, 2]
    int e = in_sizes[1] / 2;     // edge_index is [2, E]
    const int* src = ei;
    const int* dst = ei + e;

    const int TB = 256;
    int nb_n = (n + TB - 1) / TB;
    int nb_e = (e + TB - 1) / TB;

    k_init_deg<<<nb_n, TB>>>(n);
    k_count_deg<<<nb_e, TB>>>(dst, e);
    k_node1<<<nb_n, TB>>>(x, W1, n);
    k_edge1<<<nb_e, TB>>>(src, dst, e);
    k_node2<<<nb_n, TB>>>(W2, b1, b2, out, n);
    k_edge2<<<nb_e, TB>>>(src, dst, out, e);
}

// round 2
// speedup vs baseline: 1.8334x; 1.8334x over previous
#include <cuda_runtime.h>

#define NN 200000

// Scratch (alloc-free: __device__ globals)
__device__ float  g_deg[NN];      // degree incl. self-loop
__device__ float  g_dis[NN];      // deg^{-1/2}
__device__ float2 g_xs[NN];       // x[i] * dis[i]           (layer-1 pre-scaled msg)
__device__ float2 g_aggx[NN];     // Sum of dis[s]*x[s] over in-edges + self
__device__ float4 g_zs[NN];       // z[i] * dis[i]           (layer-2 pre-scaled msg)

__device__ __forceinline__ void red_add_f32(float* p, float v) {
    asm volatile("red.global.add.f32 [%0], %1;" :: "l"(p), "f"(v) : "memory");
}
__device__ __forceinline__ void red_add_v2(float2* p, float a, float b) {
    asm volatile("red.global.add.v2.f32 [%0], {%1, %2};"
                 :: "l"(p), "f"(a), "f"(b) : "memory");
}
__device__ __forceinline__ void red_add_v4(float4* p, float a, float b, float c, float d) {
    asm volatile("red.global.add.v4.f32 [%0], {%1, %2, %3, %4};"
                 :: "l"(p), "f"(a), "f"(b), "f"(c), "f"(d) : "memory");
}

// --- 1. init degree with self-loop contribution ------------------------------
__global__ void k_init_deg(int n) {
    int i = blockIdx.x * blockDim.x + threadIdx.x;
    if (i < n) g_deg[i] = 1.0f;
}

// --- 2. count in-degree at dst ------------------------------------------------
__global__ void k_count_deg(const int* __restrict__ dst, int e) {
    int i = blockIdx.x * blockDim.x + threadIdx.x;
    if (i < e) red_add_f32(&g_deg[dst[i]], 1.0f);
}

// --- 3. per-node: dis, xs = x*dis, aggx init = self-loop term (= xs) ----------
__global__ void k_node1(const float2* __restrict__ x, int n) {
    int i = blockIdx.x * blockDim.x + threadIdx.x;
    if (i >= n) return;
    float dis = rsqrtf(g_deg[i]);
    g_dis[i] = dis;
    float2 xv = x[i];
    float2 xs = make_float2(xv.x * dis, xv.y * dis);
    g_xs[i]   = xs;
    g_aggx[i] = xs;   // self loop: norm = dis[i]^2, final dis[i] applied later
}

// --- 4. layer-1 edge scatter: pure gather(8B) + red(8B) -----------------------
__global__ void k_edge1(const int* __restrict__ src,
                        const int* __restrict__ dst, int e) {
    int i = blockIdx.x * blockDim.x + threadIdx.x;
    if (i >= e) return;
    int s = src[i], t = dst[i];
    float2 m = __ldg(&g_xs[s]);
    red_add_v2(&g_aggx[t], m.x, m.y);
}

// --- 5. per-node: full layer-1 (W1,b1,relu) + layer-2 transform (W2) ----------
//        zs = z*dis ; init out accumulation = self-loop term (= zs)
__global__ void k_node2(const float* __restrict__ W1,
                        const float* __restrict__ b1,
                        const float* __restrict__ W2,
                        float4* __restrict__ out, int n) {
    int i = blockIdx.x * blockDim.x + threadIdx.x;
    if (i >= n) return;
    float dis = g_dis[i];
    float2 m = g_aggx[i];
    float m0 = m.x * dis, m1 = m.y * dis;   // agg of x @ identity, dst-scaled
    float z[4] = {0.f, 0.f, 0.f, 0.f};
#pragma unroll
    for (int k = 0; k < 8; k++) {
        float v = fmaxf(fmaf(m0, __ldg(&W1[k]), fmaf(m1, __ldg(&W1[8 + k]), __ldg(&b1[k]))), 0.0f);
#pragma unroll
        for (int j = 0; j < 4; j++)
            z[j] = fmaf(v, __ldg(&W2[k * 4 + j]), z[j]);
    }
    float4 zs = make_float4(z[0] * dis, z[1] * dis, z[2] * dis, z[3] * dis);
    g_zs[i] = zs;
    out[i]  = zs;      // self-loop init for layer-2 aggregation
}

// --- 6. layer-2 edge scatter: gather(16B) + red(16B) into d_out ---------------
__global__ void k_edge2(const int* __restrict__ src,
                        const int* __restrict__ dst,
                        float4* __restrict__ out, int e) {
    int i = blockIdx.x * blockDim.x + threadIdx.x;
    if (i >= e) return;
    int s = src[i], t = dst[i];
    float4 m = __ldg(&g_zs[s]);
    red_add_v4(&out[t], m.x, m.y, m.z, m.w);
}

// --- 7. final dst scale + bias -------------------------------------------------
__global__ void k_final(const float* __restrict__ b2,
                        float4* __restrict__ out, int n) {
    int i = blockIdx.x * blockDim.x + threadIdx.x;
    if (i >= n) return;
    float dis = g_dis[i];
    float4 v = out[i];
    out[i] = make_float4(fmaf(v.x, dis, __ldg(&b2[0])),
                         fmaf(v.y, dis, __ldg(&b2[1])),
                         fmaf(v.z, dis, __ldg(&b2[2])),
                         fmaf(v.w, dis, __ldg(&b2[3])));
}

extern "C" void kernel_launch(void* const* d_in, const int* in_sizes, int n_in,
                              void* d_out, int out_size) {
    const float* x  = (const float*)d_in[0];
    const int*   ei = (const int*)d_in[1];
    const float* W1 = (const float*)d_in[2];
    const float* b1 = (const float*)d_in[3];
    const float* W2 = (const float*)d_in[4];
    const float* b2 = (const float*)d_in[5];
    float4* out = (float4*)d_out;

    int n = in_sizes[0] / 2;     // x is [N, 2]
    int e = in_sizes[1] / 2;     // edge_index is [2, E]
    const int* src = ei;
    const int* dst = ei + e;

    const int TB = 256;
    int nb_n = (n + TB - 1) / TB;
    int nb_e = (e + TB - 1) / TB;

    k_init_deg<<<nb_n, TB>>>(n);
    k_count_deg<<<nb_e, TB>>>(dst, e);
    k_node1<<<nb_n, TB>>>((const float2*)x, n);
    k_edge1<<<nb_e, TB>>>(src, dst, e);
    k_node2<<<nb_n, TB>>>(W1, b1, W2, out, n);
    k_edge2<<<nb_e, TB>>>(src, dst, out, e);
    k_final<<<nb_n, TB>>>(b2, out, n);
}